// round 16
// baseline (speedup 1.0000x reference)
#include <cuda_runtime.h>
#include <math.h>

#define IMG     256
#define NFACE   512
#define NVERT   4096
#define NPIX    (IMG * IMG)
#define TPB     128                  // threads per block
#define NBLK    256                  // 256 blocks * 128 thr * 2 px = 65536 px
#define NGRP    (NFACE / 4)          // 128 groups of 4 faces

// Scratch (no cudaMalloc allowed)
__device__ float2 g_pv[NVERT];            // projected (x,y) per vertex
__device__ float4 g_coef[NFACE * 3];      // per-face/per-edge affine coeffs (A,B,C,_), log2-scaled
__device__ float  g_partial[NBLK];        // per-block loss partials
__device__ int    g_flag;                 // setup-done flag  (reset each run by last block)
__device__ int    g_count;                // blocks-done counter (reset each run by last block)

__device__ __forceinline__ float ex2f(float x) {
    float r; asm("ex2.approx.ftz.f32 %0, %1;" : "=f"(r) : "f"(x)); return r;
}
__device__ __forceinline__ float lg2f(float x) {
    float r; asm("lg2.approx.ftz.f32 %0, %1;" : "=f"(r) : "f"(x)); return r;
}

struct Cam {
    float ex, ey, ez;
    float r00, r01, r02, r10, r11, r12, r20, r21, r22;
    float tanv;
};

// ---------------- Single fused kernel ----------------
// Block 0: setup (vertex transform + face coefs) -> flag. Other blocks spin on flag
// (dependency only on block 0, which is always scheduled in wave 1 -> no deadlock).
// All blocks: stage coefs to smem, each thread renders 2 pixels (same column) over
// all 512 faces in groups of 4 (log2-domain product trick: 1 LG2 per 4 faces),
// computes its 2 loss terms, block-reduces, and the LAST block (atomic counter)
// does the deterministic fixed-order final reduction + writes out + resets flags.
__global__ void __launch_bounds__(TPB) k_all(const float* __restrict__ verts,
                                             const int*   __restrict__ faces,
                                             const float* __restrict__ imgref,
                                             float*       __restrict__ out,
                                             Cam cam) {
    __shared__ float4 sc[NFACE * 3];   // 24 KB
    __shared__ float  red[TPB];
    __shared__ int    lastFlag;

    const int tid = threadIdx.x;
    const int bid = blockIdx.x;

    // ---- Phase 0: setup by block 0; others wait on flag ----
    if (bid == 0) {
#pragma unroll
        for (int r = 0; r < NVERT / TPB; r++) {          // 32 verts/thread
            int i = r * TPB + tid;
            float vx = verts[i * 3 + 0] - cam.ex;
            float vy = verts[i * 3 + 1] - cam.ey;
            float vz = verts[i * 3 + 2] - cam.ez;
            float X = cam.r00 * vx + cam.r01 * vy + cam.r02 * vz;
            float Y = cam.r10 * vx + cam.r11 * vy + cam.r12 * vz;
            float Z = cam.r20 * vx + cam.r21 * vy + cam.r22 * vz;
            float denom = Z * cam.tanv + 1e-8f;
            g_pv[i] = make_float2(X / denom, Y / denom);
        }
        __syncthreads();
        const float SCALE = 144.26950408889634f;         // (1/0.01) * log2(e)
#pragma unroll
        for (int r = 0; r < NFACE / TPB; r++) {          // 4 faces/thread
            int f = r * TPB + tid;
            int i0 = faces[f * 3 + 0];
            int i1 = faces[f * 3 + 1];
            int i2 = faces[f * 3 + 2];
            float2 a = g_pv[i0], b = g_pv[i1], c = g_pv[i2];
            float area = (b.x - a.x) * (c.y - a.y) - (b.y - a.y) * (c.x - a.x);
            float sgn = (area >= 0.0f) ? 1.0f : -1.0f;
            float2 p0s[3] = { a, b, c };
            float2 p1s[3] = { b, c, a };
#pragma unroll
            for (int e = 0; e < 3; e++) {
                float exx = p1s[e].x - p0s[e].x;
                float eyy = p1s[e].y - p0s[e].y;
                float il = rsqrtf(exx * exx + eyy * eyy + 1e-8f);
                float k = il * sgn * SCALE;
                g_coef[f * 3 + e] = make_float4(-eyy * k, exx * k,
                                                (eyy * p0s[e].x - exx * p0s[e].y) * k, 0.0f);
            }
        }
        __syncthreads();
        if (tid == 0) { __threadfence(); atomicExch(&g_flag, 1); }
    } else {
        if (tid == 0) {
            while (atomicAdd(&g_flag, 0) == 0) { }
            __threadfence();
        }
        __syncthreads();
    }

    // ---- Phase 1: stage coefficients to smem (broadcast-read later) ----
    for (int i = tid; i < NFACE * 3; i += TPB) sc[i] = g_coef[i];
    __syncthreads();

    // ---- Phase 2: render 2 pixels (same column), all 512 faces ----
    const int TT  = bid * TPB + tid;          // 0..32767
    const int col = TT & (IMG - 1);
    const int rp  = TT >> 8;                  // row pair 0..127
    const float px  = (col + 0.5f) * (2.0f / 256.0f) - 1.0f;
    const float py0 = -(((2 * rp)     + 0.5f) * (2.0f / 256.0f) - 1.0f);
    const float py1 = -(((2 * rp + 1) + 0.5f) * (2.0f / 256.0f) - 1.0f);

    const float CLMP = 19.912537f;            // -log2(1 - fp32(1-1e-6)) = 24 - log2(17)

    float S0 = 0.0f, S1 = 0.0f;

#pragma unroll 2
    for (int g = 0; g < NGRP; g++) {
        float cy[12], u[12];
#pragma unroll
        for (int e = 0; e < 12; e++) {
            float4 c = sc[g * 12 + e];
            cy[e] = c.y;
            u[e]  = fmaf(c.x, px, c.z);       // px-part hoisted over the 2 pixels
        }
        // pixel 0
        {
            float t[4];
#pragma unroll
            for (int f = 0; f < 4; f++) {
                float d0 = fmaf(cy[f * 3 + 0], py0, u[f * 3 + 0]);
                float d1 = fmaf(cy[f * 3 + 1], py0, u[f * 3 + 1]);
                float d2 = fmaf(cy[f * 3 + 2], py0, u[f * 3 + 2]);
                float y  = fminf(fminf(d0, d1), d2);
                t[f] = ex2f(fminf(y, CLMP));
            }
            float P01 = fmaf(t[0], t[1], t[0] + t[1]);
            float P23 = fmaf(t[2], t[3], t[2] + t[3]);
            float P   = fmaf(P01, P23, P01 + P23);     // Π(1+t)-1, bounded 2^79.7
            S0 += lg2f(1.0f + P);
        }
        // pixel 1
        {
            float t[4];
#pragma unroll
            for (int f = 0; f < 4; f++) {
                float d0 = fmaf(cy[f * 3 + 0], py1, u[f * 3 + 0]);
                float d1 = fmaf(cy[f * 3 + 1], py1, u[f * 3 + 1]);
                float d2 = fmaf(cy[f * 3 + 2], py1, u[f * 3 + 2]);
                float y  = fminf(fminf(d0, d1), d2);
                t[f] = ex2f(fminf(y, CLMP));
            }
            float P01 = fmaf(t[0], t[1], t[0] + t[1]);
            float P23 = fmaf(t[2], t[3], t[2] + t[3]);
            float P   = fmaf(P01, P23, P01 + P23);
            S1 += lg2f(1.0f + P);
        }
    }

    // ---- Phase 3: loss for this thread's 2 pixels, block reduce ----
    float sil0 = 1.0f - ex2f(-S0);
    float sil1 = 1.0f - ex2f(-S1);
    float e0 = sil0 - imgref[(2 * rp)     * IMG + col];
    float e1 = sil1 - imgref[(2 * rp + 1) * IMG + col];
    red[tid] = fmaf(e0, e0, e1 * e1);
    __syncthreads();
    if (tid < 64) red[tid] += red[tid + 64];
    __syncthreads();
    if (tid < 32) {
        float v = red[tid] + red[tid + 32];
#pragma unroll
        for (int o = 16; o > 0; o >>= 1)
            v += __shfl_down_sync(0xFFFFFFFF, v, o);
        if (tid == 0) g_partial[bid] = v;
    }

    // ---- Phase 4: last-done block does deterministic final reduction ----
    if (tid == 0) {
        __threadfence();
        int old = atomicAdd(&g_count, 1);
        lastFlag = (old == (int)gridDim.x - 1) ? 1 : 0;
    }
    __syncthreads();
    if (lastFlag) {
        __threadfence();
        float v = __ldcg(&g_partial[tid]) + __ldcg(&g_partial[tid + TPB]);
        red[tid] = v;
        __syncthreads();
        if (tid < 64) red[tid] += red[tid + 64];
        __syncthreads();
        if (tid < 32) {
            float w = red[tid] + red[tid + 32];
#pragma unroll
            for (int o = 16; o > 0; o >>= 1)
                w += __shfl_down_sync(0xFFFFFFFF, w, o);
            if (tid == 0) {
                out[0] = w;
                g_count = 0;      // reset for next graph replay
                g_flag  = 0;
            }
        }
    }
}

extern "C" void kernel_launch(void* const* d_in, const int* in_sizes, int n_in,
                              void* d_out, int out_size) {
    const float* verts = nullptr;
    const int*   faces = nullptr;
    const float* img   = nullptr;
    for (int i = 0; i < n_in; i++) {
        if (in_sizes[i] == NVERT * 3)      verts = (const float*)d_in[i];
        else if (in_sizes[i] == NFACE * 3) faces = (const int*)d_in[i];
        else if (in_sizes[i] == NPIX)      img   = (const float*)d_in[i];
    }

    // Camera constants (host-side double; deviation vs fp32 reference ~1e-7)
    double dist = 2.732, el = 0.0, az = 90.0 * M_PI / 180.0;
    double ex = dist * cos(el) * sin(az);
    double ey = dist * sin(el);
    double ez = -dist * cos(el) * cos(az);
    double zx = -ex, zy = -ey, zz = -ez;
    double zn = sqrt(zx * zx + zy * zy + zz * zz) + 1e-8;
    zx /= zn; zy /= zn; zz /= zn;
    double xx = zz, xy = 0.0, xz = -zx;                 // cross(up, z)
    double xn = sqrt(xx * xx + xy * xy + xz * xz) + 1e-8;
    xx /= xn; xy /= xn; xz /= xn;
    double yx = zy * xz - zz * xy;                      // cross(z, x)
    double yy = zz * xx - zx * xz;
    double yz = zx * xy - zy * xx;
    double yn = sqrt(yx * yx + yy * yy + yz * yz) + 1e-8;
    yx /= yn; yy /= yn; yz /= yn;

    Cam cam;
    cam.ex = (float)ex; cam.ey = (float)ey; cam.ez = (float)ez;
    cam.r00 = (float)xx; cam.r01 = (float)xy; cam.r02 = (float)xz;
    cam.r10 = (float)yx; cam.r11 = (float)yy; cam.r12 = (float)yz;
    cam.r20 = (float)zx; cam.r21 = (float)zy; cam.r22 = (float)zz;
    cam.tanv = (float)tan(30.0 * M_PI / 180.0);

    k_all<<<NBLK, TPB>>>(verts, faces, img, (float*)d_out, cam);
}